// round 16
// baseline (speedup 1.0000x reference)
#include <cuda_runtime.h>
#include <cstdint>

// TreeNLLLoss — warp-uniform gather formulation.
// R14/R15 established the binding resource: L1tex wavefronts at 2.07 cyc/wf
// for divergent 32-lane LDGs. This round issues every random access as a
// WARP-UNIFORM LDG (shfl-broadcast index -> all lanes same address -> 1
// wavefront) which streams at the cross-LDG rate of ~1.0 cyc/wf.
//   A) node_sweep: rec[v] = {unary[v,labels[v]], labels[v]} (8 MB)
//   B) edge_kernel: per edge 3 uniform gathers: rec[child] (val+tc in one
//      8B load), label[parent], edge_pot[e,16tc+tp] (.L2::64B fill).
//      All lanes accumulate identical sums -> no warp shuffle reduction.
// E = 1,000,000, N = 1,000,001, C = 16.

#define C 16
#define THREADS 256
#define WARPS_PER_BLOCK 8
#define TILES_PER_WARP 4          // 4 tiles x 32 edges = 128 edges per warp
#define EDGES_PER_BLOCK (THREADS * TILES_PER_WARP)   // 1024
#define MAX_BLOCKS 4096
#define N_MAX 1000960

__device__ uint2    g_rec[N_MAX];          // {f32 val bits, label}
__device__ float    g_partials[MAX_BLOCKS];
__device__ unsigned g_count = 0;           // returns to 0 each replay

__device__ __forceinline__ float ld_cs_64B(const float* p)
{
    float v;
    asm("ld.global.cs.L2::64B.f32 %0, [%1];" : "=f"(v) : "l"(p));
    return v;
}

// ── Kernel A: node sweep (lane-consecutive: unary read is 64B-strided) ──
__global__ void __launch_bounds__(THREADS)
node_sweep(const float* __restrict__ unary,
           const int*   __restrict__ labels,
           int N)
{
    const int block_base = blockIdx.x * (THREADS * 4);
    #pragma unroll
    for (int j = 0; j < 4; j++) {
        int v = block_base + j * THREADS + threadIdx.x;
        if (v < N) {
            int lab = __ldg(&labels[v]);
            float val = __ldg(&unary[(size_t)v * C + lab]);
            uint2 r;
            r.x = __float_as_uint(val);
            r.y = (unsigned)lab;
            g_rec[v] = r;
        }
    }
}

// ── Kernel B: warp-uniform edge gathers + reduce + finalize ──
__global__ void __launch_bounds__(THREADS)
edge_kernel(const float* __restrict__ edge_pot,
            const int*   __restrict__ child_idx,
            const int*   __restrict__ parent_idx,
            const int*   __restrict__ root_idx,
            const float* __restrict__ partition,
            float* __restrict__ out,
            int E)
{
    const int lane = threadIdx.x & 31;
    const int wid  = threadIdx.x >> 5;

    float s = 0.0f;   // identical on all lanes of a warp

    const int warp_global = blockIdx.x * WARPS_PER_BLOCK + wid;

    #pragma unroll
    for (int t = 0; t < TILES_PER_WARP; t++) {
        const int ebase = (warp_global * TILES_PER_WARP + t) * 32;
        if (ebase >= E) break;
        const int nvalid = min(32, E - ebase);

        // coalesced per-lane index loads (1 line each)
        int e = ebase + lane;
        bool v = (e < E);
        int c = v ? __ldg(&child_idx[e])  : 0;
        int p = v ? __ldg(&parent_idx[e]) : 0;

        // chunks of 8 edges: broadcast index -> uniform gathers
        for (int j0 = 0; j0 < nvalid; j0 += 8) {
            uint2    rc[8];
            unsigned tp[8];
            #pragma unroll
            for (int jj = 0; jj < 8; jj++) {
                int j  = j0 + jj;
                int cj = __shfl_sync(0xffffffffu, c, j);
                int pj = __shfl_sync(0xffffffffu, p, j);
                rc[jj] = __ldg(&g_rec[cj]);                       // uniform, 1 wf
                tp[jj] = __ldg(((const unsigned*)g_rec) + 2 * pj + 1); // uniform, 1 wf
            }
            float ep[8];
            #pragma unroll
            for (int jj = 0; jj < 8; jj++) {
                int j = j0 + jj;
                ep[jj] = (j < nvalid)
                    ? ld_cs_64B(&edge_pot[(size_t)(ebase + j) * (C * C)
                                          + rc[jj].y * C + tp[jj]])  // uniform, 1 wf
                    : 0.0f;
            }
            #pragma unroll
            for (int jj = 0; jj < 8; jj++) {
                int j = j0 + jj;
                if (j < nvalid)
                    s += ep[jj] + __uint_as_float(rc[jj].x);
            }
        }
    }

    // per-warp sum is already complete on every lane — no shuffle reduce.
    __shared__ float warp_sums[WARPS_PER_BLOCK];
    if (lane == 0) warp_sums[wid] = s;
    __syncthreads();

    if (wid == 0) {
        float bsum = (lane < WARPS_PER_BLOCK) ? warp_sums[lane] : 0.0f;
        #pragma unroll
        for (int off = 4; off > 0; off >>= 1)
            bsum += __shfl_down_sync(0xffffffffu, bsum, off);
        if (lane == 0) g_partials[blockIdx.x] = bsum;
    }

    // ── last-block-done finalize ──
    __shared__ bool is_last;
    __threadfence();
    if (threadIdx.x == 0) {
        unsigned ticket = atomicAdd(&g_count, 1u);
        is_last = (ticket == gridDim.x - 1);
    }
    __syncthreads();

    if (is_last) {
        double acc = 0.0;
        for (int i = threadIdx.x; i < (int)gridDim.x; i += THREADS)
            acc += (double)__ldcg(&g_partials[i]);

        #pragma unroll
        for (int off = 16; off > 0; off >>= 1)
            acc += __shfl_down_sync(0xffffffffu, acc, off);

        __shared__ double dwarp[THREADS / 32];
        if (lane == 0) dwarp[wid] = acc;
        __syncthreads();

        if (wid == 0) {
            double tt = (lane < THREADS / 32) ? dwarp[lane] : 0.0;
            #pragma unroll
            for (int off = 4; off > 0; off >>= 1)
                tt += __shfl_down_sync(0xffffffffu, tt, off);
            if (lane == 0) {
                int r = __ldg(root_idx);
                uint2 rr = g_rec[r];
                double loss = tt + (double)__uint_as_float(rr.x);
                out[0] = -(float)(loss - (double)__ldg(partition));
                g_count = 0;   // reset for next replay
            }
        }
    }
}

extern "C" void kernel_launch(void* const* d_in, const int* in_sizes, int n_in,
                              void* d_out, int out_size)
{
    const float* edge_pot   = (const float*)d_in[0];
    const float* unary      = (const float*)d_in[1];
    const int*   labels     = (const int*)d_in[2];
    const int*   child_idx  = (const int*)d_in[3];
    const int*   parent_idx = (const int*)d_in[4];
    const int*   root_idx   = (const int*)d_in[5];
    const float* partition  = (const float*)d_in[6];
    float* out = (float*)d_out;

    int N = in_sizes[2];
    int E = in_sizes[3];

    int sweep_blocks = (N + THREADS * 4 - 1) / (THREADS * 4);   // 977
    node_sweep<<<sweep_blocks, THREADS>>>(unary, labels, N);

    int blocks = (E + EDGES_PER_BLOCK - 1) / EDGES_PER_BLOCK;   // 977
    if (blocks > MAX_BLOCKS) blocks = MAX_BLOCKS;

    edge_kernel<<<blocks, THREADS>>>(edge_pot, child_idx, parent_idx,
                                     root_idx, partition, out, E);
}

// round 17
// speedup vs baseline: 1.2985x; 1.2985x over previous
#include <cuda_runtime.h>
#include <cstdint>

// TreeNLLLoss — R15 structure (best 33.3us) + residency trims.
// Floor model (validated R14/R15/R16): 3 random scalar accesses per edge,
// ~2.07 cyc/wavefront/SM aggregate => edge kernel floor ~23.5us.
//   A) node_sweep: rec[v] = {unary[v,labels[v]], labels[v]} (8 MB)
//                  labels8[v] = u8 label (1 MB, L2-resident)
//   B) edge_kernel: rec[child] (val+tc, one 8B gather, .L2::64B),
//      labels8[parent] (1B, L2-hit), edge_pot[e,16tc+tp] (.L2::64B).
//   loss = sum_e ep + sum_e val_child + val_root;  out = -(loss - partition)
// E = 1,000,000, N = 1,000,001, C = 16.

#define C 16
#define EPT 4
#define THREADS 256
#define MAX_BLOCKS 4096
#define N_MAX 1000960

__device__ uint2         g_rec[N_MAX];       // {f32 val bits, label}
__device__ unsigned char g_labels8[N_MAX];   // 1 MB
__device__ float         g_partials[MAX_BLOCKS];
__device__ unsigned      g_count = 0;        // returns to 0 each replay

// edge_pot: evict-first + 64B fetch granularity
__device__ __forceinline__ float ld_cs_64B(const float* p)
{
    float v;
    asm("ld.global.cs.L2::64B.f32 %0, [%1];" : "=f"(v) : "l"(p));
    return v;
}

// rec: read-only + 64B fetch granularity (8B payload)
__device__ __forceinline__ uint2 ld_rec_64B(const uint2* p)
{
    uint2 v;
    asm("ld.global.nc.L2::64B.v2.u32 {%0,%1}, [%2];"
        : "=r"(v.x), "=r"(v.y) : "l"(p));
    return v;
}

// ── Kernel A: node sweep (lane-consecutive: unary read is 64B-strided) ──
__global__ void __launch_bounds__(THREADS)
node_sweep(const float* __restrict__ unary,
           const int*   __restrict__ labels,
           int N)
{
    const int block_base = blockIdx.x * (THREADS * 4);
    #pragma unroll
    for (int j = 0; j < 4; j++) {
        int v = block_base + j * THREADS + threadIdx.x;
        if (v < N) {
            int lab = __ldg(&labels[v]);
            float val = __ldg(&unary[(size_t)v * C + lab]);
            uint2 r;
            r.x = __float_as_uint(val);
            r.y = (unsigned)lab;
            g_rec[v] = r;
            g_labels8[v] = (unsigned char)lab;
        }
    }
}

// ── Kernel B: edge gathers (3 random wf/edge) + reduce + finalize ──
__global__ void __launch_bounds__(THREADS)
edge_kernel(const float* __restrict__ edge_pot,
            const int*   __restrict__ child_idx,
            const int*   __restrict__ parent_idx,
            const int*   __restrict__ root_idx,
            const float* __restrict__ partition,
            float* __restrict__ out,
            int E)
{
    const int tid  = blockIdx.x * THREADS + threadIdx.x;
    const int base = tid * EPT;

    float s = 0.0f;

    if (base + EPT <= E) {
        // coalesced index streams
        int4 c4 = __ldg((const int4*)child_idx  + tid);
        int4 p4 = __ldg((const int4*)parent_idx + tid);
        int c[EPT] = {c4.x, c4.y, c4.z, c4.w};
        int p[EPT] = {p4.x, p4.y, p4.z, p4.w};

        // child record: unary value + child label in ONE 8B gather
        uint2 rc[EPT];
        #pragma unroll
        for (int j = 0; j < EPT; j++)
            rc[j] = ld_rec_64B(&g_rec[c[j]]);

        // parent label from 1 MB u8 array (L2-resident)
        unsigned tp[EPT];
        #pragma unroll
        for (int j = 0; j < EPT; j++)
            tp[j] = (unsigned)__ldg(&g_labels8[p[j]]);

        // edge potential gather (64B fill, evict-first)
        float ep[EPT];
        #pragma unroll
        for (int j = 0; j < EPT; j++)
            ep[j] = ld_cs_64B(&edge_pot[(size_t)(base + j) * (C * C)
                                        + rc[j].y * C + tp[j]]);

        #pragma unroll
        for (int j = 0; j < EPT; j++)
            s += ep[j] + __uint_as_float(rc[j].x);
    } else {
        for (int j = 0; j < EPT; j++) {
            int e = base + j;
            if (e < E) {
                int ci = __ldg(&child_idx[e]);
                int pi = __ldg(&parent_idx[e]);
                uint2 rc = ld_rec_64B(&g_rec[ci]);
                unsigned tp = (unsigned)__ldg(&g_labels8[pi]);
                s += ld_cs_64B(&edge_pot[(size_t)e * (C * C) + rc.y * C + tp]);
                s += __uint_as_float(rc.x);
            }
        }
    }

    // ── block reduce ──
    #pragma unroll
    for (int off = 16; off > 0; off >>= 1)
        s += __shfl_down_sync(0xffffffffu, s, off);

    __shared__ float warp_sums[THREADS / 32];
    const int lane = threadIdx.x & 31;
    const int wid  = threadIdx.x >> 5;
    if (lane == 0) warp_sums[wid] = s;
    __syncthreads();

    if (wid == 0) {
        float t = (lane < THREADS / 32) ? warp_sums[lane] : 0.0f;
        #pragma unroll
        for (int off = 4; off > 0; off >>= 1)
            t += __shfl_down_sync(0xffffffffu, t, off);
        if (lane == 0) g_partials[blockIdx.x] = t;
    }

    // ── last-block-done finalize ──
    __shared__ bool is_last;
    __threadfence();
    if (threadIdx.x == 0) {
        unsigned ticket = atomicAdd(&g_count, 1u);
        is_last = (ticket == gridDim.x - 1);
    }
    __syncthreads();

    if (is_last) {
        double acc = 0.0;
        for (int i = threadIdx.x; i < (int)gridDim.x; i += THREADS)
            acc += (double)__ldcg(&g_partials[i]);

        #pragma unroll
        for (int off = 16; off > 0; off >>= 1)
            acc += __shfl_down_sync(0xffffffffu, acc, off);

        __shared__ double dwarp[THREADS / 32];
        if (lane == 0) dwarp[wid] = acc;
        __syncthreads();

        if (wid == 0) {
            double t = (lane < THREADS / 32) ? dwarp[lane] : 0.0;
            #pragma unroll
            for (int off = 4; off > 0; off >>= 1)
                t += __shfl_down_sync(0xffffffffu, t, off);
            if (lane == 0) {
                int r = __ldg(root_idx);
                uint2 rr = g_rec[r];
                double loss = t + (double)__uint_as_float(rr.x);
                out[0] = -(float)(loss - (double)__ldg(partition));
                g_count = 0;   // reset for next replay
            }
        }
    }
}

extern "C" void kernel_launch(void* const* d_in, const int* in_sizes, int n_in,
                              void* d_out, int out_size)
{
    const float* edge_pot   = (const float*)d_in[0];
    const float* unary      = (const float*)d_in[1];
    const int*   labels     = (const int*)d_in[2];
    const int*   child_idx  = (const int*)d_in[3];
    const int*   parent_idx = (const int*)d_in[4];
    const int*   root_idx   = (const int*)d_in[5];
    const float* partition  = (const float*)d_in[6];
    float* out = (float*)d_out;

    int N = in_sizes[2];
    int E = in_sizes[3];

    int sweep_blocks = (N + THREADS * 4 - 1) / (THREADS * 4);   // 977
    node_sweep<<<sweep_blocks, THREADS>>>(unary, labels, N);

    int per_block = THREADS * EPT;
    int blocks = (E + per_block - 1) / per_block;
    if (blocks > MAX_BLOCKS) blocks = MAX_BLOCKS;               // 977

    edge_kernel<<<blocks, THREADS>>>(edge_pot, child_idx, parent_idx,
                                     root_idx, partition, out, E);
}